// round 1
// baseline (speedup 1.0000x reference)
#include <cuda_runtime.h>
#include <math.h>

// ---------------- problem constants ----------------
#define B_    2
#define T_    1024
#define C_    1024
#define H_    16
#define HD_   64
#define DC_   256
#define DC1_  256
#define DR_   32      // rope dim
#define DN_   32      // nope dim
#define V_    32000
#define L_    4
#define NTOK  (B_*T_)             // 2048
#define DOWNW (DC_+DC1_+DR_)      // 544
#define KVW   (H_*(DN_+HD_))      // 1536
#define EPS_  1.1920929e-07f

// ---------------- scratch (device globals; no allocation allowed) ----------
__device__ float g_x   [NTOK*C_];
__device__ float g_x0  [NTOK*C_];
__device__ float g_xn  [NTOK*C_];
__device__ float g_down[NTOK*DOWNW];
__device__ float g_kv  [NTOK*KVW];
__device__ float g_qpre[NTOK*C_];
__device__ float g_q   [NTOK*C_];
__device__ float g_k   [NTOK*C_];
__device__ float g_v   [NTOK*C_];
__device__ float g_y   [NTOK*C_];
__device__ float g_h   [NTOK*4*C_];

// ---------------- helpers ----------------
__device__ __forceinline__ float warp_sum(float v) {
    v += __shfl_xor_sync(0xffffffffu, v, 16);
    v += __shfl_xor_sync(0xffffffffu, v, 8);
    v += __shfl_xor_sync(0xffffffffu, v, 4);
    v += __shfl_xor_sync(0xffffffffu, v, 2);
    v += __shfl_xor_sync(0xffffffffu, v, 1);
    return v;
}

__device__ __forceinline__ float block_sum(float v) {
    __shared__ float sh[32];
    int lane = threadIdx.x & 31, wid = threadIdx.x >> 5;
    v = warp_sum(v);
    if (lane == 0) sh[wid] = v;
    __syncthreads();
    int nw = blockDim.x >> 5;
    if (wid == 0) {
        float t = (lane < nw) ? sh[lane] : 0.f;
        t = warp_sum(t);
        if (lane == 0) sh[0] = t;
    }
    __syncthreads();
    return sh[0];
}

// ---------------- embedding + rmsnorm -> x, x0 ----------------
__global__ void embed_kernel(const int* __restrict__ idx, const float* __restrict__ wte) {
    int row = blockIdx.x;
    int tok = idx[row];
    const float* src = wte + (size_t)tok * C_;
    float s = 0.f;
    for (int i = threadIdx.x; i < C_; i += blockDim.x) { float v = src[i]; s += v * v; }
    s = block_sum(s);
    float r = rsqrtf(s * (1.0f / C_) + EPS_);
    for (int i = threadIdx.x; i < C_; i += blockDim.x) {
        float v = src[i] * r;
        g_x [(size_t)row * C_ + i] = v;
        g_x0[(size_t)row * C_ + i] = v;
    }
}

// ---------------- x = rl*x + xl*x0 (optional); xn = rmsnorm(x) ----------------
__global__ void mix_norm_kernel(const float* lr, const float* lx, int layer) {
    int row = blockIdx.x;
    float a = lr ? lr[layer] : 1.0f;
    float b = lx ? lx[layer] : 0.0f;
    float*       xr  = g_x  + (size_t)row * C_;
    const float* x0r = g_x0 + (size_t)row * C_;
    float s = 0.f;
    for (int i = threadIdx.x; i < C_; i += blockDim.x) {
        float v = a * xr[i] + b * x0r[i];
        xr[i] = v;
        s += v * v;
    }
    s = block_sum(s);
    float r = rsqrtf(s * (1.0f / C_) + EPS_);
    for (int i = threadIdx.x; i < C_; i += blockDim.x)
        g_xn[(size_t)row * C_ + i] = xr[i] * r;
}

// ---------------- generic tiled fp32 GEMM ----------------
// C[M,N] = A[M,K] @ B[K,N]  (+ D residual)  (mode 1: softcap epilogue)
__global__ void gemm_kernel(const float* __restrict__ A, const float* __restrict__ Bm,
                            float* __restrict__ C, const float* __restrict__ D,
                            int M, int N, int K, int lda, int ldb, int ldc, int mode)
{
    __shared__ float As[64][17];
    __shared__ float Bs[16][64];
    int tid = threadIdx.x;
    int tx = tid & 15, ty = tid >> 4;
    int n0 = blockIdx.x * 64, m0 = blockIdx.y * 64;

    float acc[4][4] = {};
    for (int kt = 0; kt < K; kt += 16) {
#pragma unroll
        for (int i = tid; i < 64 * 16; i += 256) {
            int m = i >> 4, k = i & 15;
            As[m][k] = (m0 + m < M) ? A[(size_t)(m0 + m) * lda + kt + k] : 0.f;
        }
#pragma unroll
        for (int i = tid; i < 16 * 64; i += 256) {
            int k = i >> 6, n = i & 63;
            Bs[k][n] = (n0 + n < N) ? Bm[(size_t)(kt + k) * ldb + n0 + n] : 0.f;
        }
        __syncthreads();
#pragma unroll
        for (int kk = 0; kk < 16; kk++) {
            float a[4], b[4];
#pragma unroll
            for (int i = 0; i < 4; i++) a[i] = As[ty * 4 + i][kk];
            float4 b4 = *reinterpret_cast<const float4*>(&Bs[kk][tx * 4]);
            b[0] = b4.x; b[1] = b4.y; b[2] = b4.z; b[3] = b4.w;
#pragma unroll
            for (int i = 0; i < 4; i++)
#pragma unroll
                for (int j = 0; j < 4; j++)
                    acc[i][j] += a[i] * b[j];
        }
        __syncthreads();
    }
#pragma unroll
    for (int i = 0; i < 4; i++) {
        int m = m0 + ty * 4 + i;
        if (m >= M) continue;
#pragma unroll
        for (int j = 0; j < 4; j++) {
            int n = n0 + tx * 4 + j;
            if (n >= N) continue;
            float v = acc[i][j];
            if (D)         v += D[(size_t)m * ldc + n];
            if (mode == 1) v = 15.0f * tanhf(v * (1.0f / 15.0f));
            C[(size_t)m * ldc + n] = v;
        }
    }
}

// ---------------- per-token q/k/v build: gate, rope, per-head rmsnorm ------
// grid: NTOK blocks, 512 threads (16 warps = 16 heads)
__global__ void build_qkv_kernel(const int* __restrict__ idx,
                                 const float* __restrict__ cosp, const float* __restrict__ sinp,
                                 const float* __restrict__ vg, const float* __restrict__ vetab)
{
    int row = blockIdx.x;
    int h    = threadIdx.x >> 5;
    int lane = threadIdx.x & 31;
    const float* cosr = cosp + (size_t)row * (DR_ / 2);
    const float* sinr = sinp + (size_t)row * (DR_ / 2);

    // gate = 2*sigmoid(xn[:32] . vg[:,h])
    float gv = g_xn[(size_t)row * C_ + lane] * vg[lane * H_ + h];
    gv = warp_sum(gv);
    float gate = 2.0f / (1.0f + __expf(-gv));

    int r16 = (lane < 16) ? lane : lane - 16;
    float c = cosr[r16], s = sinr[r16];

    // --- k: nope (d=lane) + rope (d=lane+32), rmsnorm over 64 ---
    float kn = g_kv[(size_t)row * KVW + h * 96 + lane];
    const float* dro = g_down + (size_t)row * DOWNW + 512;
    float kr = (lane < 16) ? (dro[lane] * c + dro[lane + 16] * s)
                           : (-dro[lane - 16] * s + dro[lane] * c);
    float ssk = warp_sum(kn * kn + kr * kr);
    float rk = rsqrtf(ssk * (1.0f / 64.0f) + EPS_);
    g_k[(size_t)row * C_ + h * 64 + lane]      = kn * rk;
    g_k[(size_t)row * C_ + h * 64 + lane + 32] = kr * rk;

    // --- q: nope + rope, rmsnorm over 64 ---
    const float* qp = g_qpre + (size_t)row * C_ + h * 64;
    float qn = qp[lane];
    float qr = (lane < 16) ? (qp[32 + lane] * c + qp[48 + lane] * s)
                           : (-qp[16 + lane] * s + qp[32 + lane] * c); // 32+(lane-16)=16+lane
    float ssq = warp_sum(qn * qn + qr * qr);
    float rq = rsqrtf(ssq * (1.0f / 64.0f) + EPS_);
    g_q[(size_t)row * C_ + h * 64 + lane]      = qn * rq;
    g_q[(size_t)row * C_ + h * 64 + lane + 32] = qr * rq;

    // --- v = kv_v + gate * ve ---
    int tok = idx[row];
    const float* ver = vetab + (size_t)tok * C_ + h * 64;
    const float* kvv = g_kv + (size_t)row * KVW + h * 96 + 32;
    g_v[(size_t)row * C_ + h * 64 + lane]      = kvv[lane]      + gate * ver[lane];
    g_v[(size_t)row * C_ + h * 64 + lane + 32] = kvv[lane + 32] + gate * ver[lane + 32];
}

// ---------------- causal flash attention (fp32, online softmax) ------------
// grid: (T/64, H, B), block 256 (16x16); Q tile 64 rows, K tile 32 cols
__global__ void attn_kernel()
{
    __shared__ float Qs[64][65];
    __shared__ float Ks[32][65];
    __shared__ float VsT[64][33];
    __shared__ float Ps[64][33];

    int q0 = blockIdx.x * 64;
    int h  = blockIdx.y;
    int b  = blockIdx.z;
    int tid = threadIdx.x;
    int tx = tid & 15, ty = tid >> 4;

    for (int i = tid; i < 64 * 64; i += 256) {
        int r = i >> 6, d = i & 63;
        Qs[r][d] = g_q[((size_t)(b * T_ + q0 + r) * H_ + h) * HD_ + d];
    }

    float m[4], l[4], acc[4][4];
#pragma unroll
    for (int i = 0; i < 4; i++) {
        m[i] = -1e30f; l[i] = 0.f;
#pragma unroll
        for (int j = 0; j < 4; j++) acc[i][j] = 0.f;
    }
    __syncthreads();

    for (int k0 = 0; k0 <= q0 + 32; k0 += 32) {
        for (int i = tid; i < 32 * 64; i += 256) {
            int r = i >> 6, d = i & 63;
            float v = g_k[((size_t)(b * T_ + k0 + r) * H_ + h) * HD_ + d];
            float w = g_v[((size_t)(b * T_ + k0 + r) * H_ + h) * HD_ + d];
            Ks[r][d]  = v;
            VsT[d][r] = w;
        }
        __syncthreads();

        // S = Q @ K^T  (4x2 per thread)
        float sv[4][2] = {};
#pragma unroll
        for (int d = 0; d < 64; d++) {
            float a0 = Qs[ty * 4 + 0][d], a1 = Qs[ty * 4 + 1][d];
            float a2 = Qs[ty * 4 + 2][d], a3 = Qs[ty * 4 + 3][d];
            float b0 = Ks[tx * 2 + 0][d], b1 = Ks[tx * 2 + 1][d];
            sv[0][0] += a0 * b0; sv[0][1] += a0 * b1;
            sv[1][0] += a1 * b0; sv[1][1] += a1 * b1;
            sv[2][0] += a2 * b0; sv[2][1] += a2 * b1;
            sv[3][0] += a3 * b0; sv[3][1] += a3 * b1;
        }

#pragma unroll
        for (int i = 0; i < 4; i++) {
            int qi = q0 + ty * 4 + i;
#pragma unroll
            for (int j = 0; j < 2; j++) {
                int ki = k0 + tx * 2 + j;
                sv[i][j] = (ki <= qi) ? sv[i][j] * 0.125f : -1e30f;
            }
            float rm = fmaxf(sv[i][0], sv[i][1]);
            rm = fmaxf(rm, __shfl_xor_sync(0xffffffffu, rm, 8, 16));
            rm = fmaxf(rm, __shfl_xor_sync(0xffffffffu, rm, 4, 16));
            rm = fmaxf(rm, __shfl_xor_sync(0xffffffffu, rm, 2, 16));
            rm = fmaxf(rm, __shfl_xor_sync(0xffffffffu, rm, 1, 16));
            float mn = fmaxf(m[i], rm);
            float corr = __expf(m[i] - mn);
            float p0 = __expf(sv[i][0] - mn);
            float p1 = __expf(sv[i][1] - mn);
            float rs = p0 + p1;
            rs += __shfl_xor_sync(0xffffffffu, rs, 8, 16);
            rs += __shfl_xor_sync(0xffffffffu, rs, 4, 16);
            rs += __shfl_xor_sync(0xffffffffu, rs, 2, 16);
            rs += __shfl_xor_sync(0xffffffffu, rs, 1, 16);
            l[i] = l[i] * corr + rs;
            m[i] = mn;
#pragma unroll
            for (int j = 0; j < 4; j++) acc[i][j] *= corr;
            Ps[ty * 4 + i][tx * 2 + 0] = p0;
            Ps[ty * 4 + i][tx * 2 + 1] = p1;
        }
        __syncwarp();

        // O += P @ V   (4x4 per thread, d = tx*4+j)
#pragma unroll
        for (int k = 0; k < 32; k++) {
            float a0 = Ps[ty * 4 + 0][k], a1 = Ps[ty * 4 + 1][k];
            float a2 = Ps[ty * 4 + 2][k], a3 = Ps[ty * 4 + 3][k];
            float b0 = VsT[tx * 4 + 0][k], b1 = VsT[tx * 4 + 1][k];
            float b2 = VsT[tx * 4 + 2][k], b3 = VsT[tx * 4 + 3][k];
            acc[0][0] += a0 * b0; acc[0][1] += a0 * b1; acc[0][2] += a0 * b2; acc[0][3] += a0 * b3;
            acc[1][0] += a1 * b0; acc[1][1] += a1 * b1; acc[1][2] += a1 * b2; acc[1][3] += a1 * b3;
            acc[2][0] += a2 * b0; acc[2][1] += a2 * b1; acc[2][2] += a2 * b2; acc[2][3] += a2 * b3;
            acc[3][0] += a3 * b0; acc[3][1] += a3 * b1; acc[3][2] += a3 * b2; acc[3][3] += a3 * b3;
        }
        __syncthreads();
    }

#pragma unroll
    for (int i = 0; i < 4; i++) {
        float inv = 1.0f / l[i];
        int r = q0 + ty * 4 + i;
#pragma unroll
        for (int j = 0; j < 4; j++)
            g_y[((size_t)(b * T_ + r) * H_ + h) * HD_ + tx * 4 + j] = acc[i][j] * inv;
    }
}

// ---------------- h = relu(h)^2 in place ----------------
__global__ void relusq_kernel(int n) {
    int i = blockIdx.x * blockDim.x + threadIdx.x;
    if (i < n) {
        float v = g_h[i];
        g_h[i] = (v > 0.f) ? v * v : 0.f;
    }
}

// ---------------- host orchestration ----------------
extern "C" void kernel_launch(void* const* d_in, const int* in_sizes, int n_in,
                              void* d_out, int out_size)
{
    (void)in_sizes; (void)n_in; (void)out_size;
    const int*   idx  = (const int*)  d_in[0];
    const float* cosp = (const float*)d_in[1];
    const float* sinp = (const float*)d_in[2];
    const float* wte  = (const float*)d_in[3];
    const float* vemb = (const float*)d_in[4];
    const float* wd   = (const float*)d_in[5];
    const float* wukv = (const float*)d_in[6];
    const float* wuq  = (const float*)d_in[7];
    const float* vg   = (const float*)d_in[8];
    const float* ap   = (const float*)d_in[9];
    const float* fc   = (const float*)d_in[10];
    const float* pj   = (const float*)d_in[11];
    const float* lr   = (const float*)d_in[12];
    const float* lx   = (const float*)d_in[13];
    const float* lmh  = (const float*)d_in[14];
    float* out = (float*)d_out;

    float *px, *pxn, *pdown, *pkv, *pqpre, *py, *ph;
    cudaGetSymbolAddress((void**)&px,    g_x);
    cudaGetSymbolAddress((void**)&pxn,   g_xn);
    cudaGetSymbolAddress((void**)&pdown, g_down);
    cudaGetSymbolAddress((void**)&pkv,   g_kv);
    cudaGetSymbolAddress((void**)&pqpre, g_qpre);
    cudaGetSymbolAddress((void**)&py,    g_y);
    cudaGetSymbolAddress((void**)&ph,    g_h);

    embed_kernel<<<NTOK, 256>>>(idx, wte);

    for (int l = 0; l < L_; l++) {
        // xm = rl*x + xl*x0 ; xn = rmsnorm(xm)
        mix_norm_kernel<<<NTOK, 256>>>(lr, lx, l);

        // down = xn @ wd[l]  [2048,1024]@[1024,544]
        gemm_kernel<<<dim3((DOWNW + 63) / 64, NTOK / 64), 256>>>(
            pxn, wd + (size_t)l * C_ * DOWNW, pdown, nullptr,
            NTOK, DOWNW, C_, C_, DOWNW, DOWNW, 0);

        // kv = down[:, :256] @ wukv[l]  [2048,256]@[256,1536]
        gemm_kernel<<<dim3(KVW / 64, NTOK / 64), 256>>>(
            pdown, wukv + (size_t)l * DC_ * KVW, pkv, nullptr,
            NTOK, KVW, DC_, DOWNW, KVW, KVW, 0);

        // qpre = down[:, 256:512] @ wuq[l]  [2048,256]@[256,1024]
        gemm_kernel<<<dim3(C_ / 64, NTOK / 64), 256>>>(
            pdown + DC_, wuq + (size_t)l * DC1_ * C_, pqpre, nullptr,
            NTOK, C_, DC1_, DOWNW, C_, C_, 0);

        // build q/k/v (gate, rope, per-head rmsnorm, ve injection)
        build_qkv_kernel<<<NTOK, 512>>>(idx, cosp, sinp,
                                        vg + (size_t)l * 32 * H_,
                                        vemb + (size_t)l * V_ * C_);

        // attention
        attn_kernel<<<dim3(T_ / 64, H_, B_), 256>>>();

        // x += y @ ap[l]
        gemm_kernel<<<dim3(C_ / 64, NTOK / 64), 256>>>(
            py, ap + (size_t)l * C_ * C_, px, px,
            NTOK, C_, C_, C_, C_, C_, 0);

        // xn = rmsnorm(x)
        mix_norm_kernel<<<NTOK, 256>>>(nullptr, nullptr, 0);

        // h = xn @ fc[l]  [2048,1024]@[1024,4096]
        gemm_kernel<<<dim3(4 * C_ / 64, NTOK / 64), 256>>>(
            pxn, fc + (size_t)l * C_ * 4 * C_, ph, nullptr,
            NTOK, 4 * C_, C_, C_, 4 * C_, 4 * C_, 0);

        // h = relu(h)^2
        relusq_kernel<<<(NTOK * 4 * C_ + 255) / 256, 256>>>(NTOK * 4 * C_);

        // x += h @ pj[l]  [2048,4096]@[4096,1024]
        gemm_kernel<<<dim3(C_ / 64, NTOK / 64), 256>>>(
            ph, pj + (size_t)l * 4 * C_ * C_, px, px,
            NTOK, C_, 4 * C_, 4 * C_, C_, C_, 0);
    }

    // final: xn = rmsnorm(x); out = softcap(xn @ lm_head)
    mix_norm_kernel<<<NTOK, 256>>>(nullptr, nullptr, 0);
    gemm_kernel<<<dim3(V_ / 64, NTOK / 64), 256>>>(
        pxn, lmh, out, nullptr,
        NTOK, V_, C_, C_, V_, V_, 1);
}

// round 2
// speedup vs baseline: 2.1678x; 2.1678x over previous
#include <cuda_runtime.h>
#include <math.h>
#include <stdint.h>

// ---------------- problem constants ----------------
#define B_    2
#define T_    1024
#define C_    1024
#define H_    16
#define HD_   64
#define DC_   256
#define DC1_  256
#define DR_   32      // rope dim
#define DN_   32      // nope dim
#define V_    32000
#define L_    4
#define NTOK  (B_*T_)             // 2048
#define DOWNW (DC_+DC1_+DR_)      // 544
#define KVW   (H_*(DN_+HD_))      // 1536
#define EPS_  1.1920929e-07f

// ---------------- scratch (device globals; no allocation allowed) ----------
__device__ float g_x   [NTOK*C_];
__device__ float g_x0  [NTOK*C_];
__device__ float g_xn  [NTOK*C_];
__device__ float g_down[NTOK*DOWNW];
__device__ float g_kv  [NTOK*KVW];
__device__ float g_qpre[NTOK*C_];
__device__ float g_q   [NTOK*C_];
__device__ float g_k   [NTOK*C_];
__device__ float g_v   [NTOK*C_];
__device__ float g_y   [NTOK*C_];
__device__ float g_h   [NTOK*4*C_];

// ---------------- helpers ----------------
__device__ __forceinline__ float warp_sum(float v) {
    v += __shfl_xor_sync(0xffffffffu, v, 16);
    v += __shfl_xor_sync(0xffffffffu, v, 8);
    v += __shfl_xor_sync(0xffffffffu, v, 4);
    v += __shfl_xor_sync(0xffffffffu, v, 2);
    v += __shfl_xor_sync(0xffffffffu, v, 1);
    return v;
}

__device__ __forceinline__ float block_sum(float v) {
    __shared__ float sh[32];
    int lane = threadIdx.x & 31, wid = threadIdx.x >> 5;
    v = warp_sum(v);
    if (lane == 0) sh[wid] = v;
    __syncthreads();
    int nw = blockDim.x >> 5;
    if (wid == 0) {
        float t = (lane < nw) ? sh[lane] : 0.f;
        t = warp_sum(t);
        if (lane == 0) sh[0] = t;
    }
    __syncthreads();
    return sh[0];
}

// ---------------- tf32 split + mma ----------------
__device__ __forceinline__ void split1(float x, uint32_t& hi, uint32_t& lo) {
    uint32_t h; asm("cvt.rna.tf32.f32 %0, %1;" : "=r"(h) : "f"(x));
    float hf = __uint_as_float(h);
    float r = x - hf;
    uint32_t l; asm("cvt.rna.tf32.f32 %0, %1;" : "=r"(l) : "f"(r));
    hi = h; lo = l;
}

__device__ __forceinline__ void mma8(float4& d,
    uint32_t a0, uint32_t a1, uint32_t a2, uint32_t a3,
    uint32_t b0, uint32_t b1)
{
    asm volatile(
        "mma.sync.aligned.m16n8k8.row.col.f32.tf32.tf32.f32 "
        "{%0,%1,%2,%3},{%4,%5,%6,%7},{%8,%9},{%0,%1,%2,%3};"
        : "+f"(d.x), "+f"(d.y), "+f"(d.z), "+f"(d.w)
        : "r"(a0), "r"(a1), "r"(a2), "r"(a3), "r"(b0), "r"(b1));
}

// ---------------- embedding + rmsnorm -> x, x0 ----------------
__global__ void embed_kernel(const int* __restrict__ idx, const float* __restrict__ wte) {
    int row = blockIdx.x;
    int tok = idx[row];
    const float* src = wte + (size_t)tok * C_;
    float s = 0.f;
    for (int i = threadIdx.x; i < C_; i += blockDim.x) { float v = src[i]; s += v * v; }
    s = block_sum(s);
    float r = rsqrtf(s * (1.0f / C_) + EPS_);
    for (int i = threadIdx.x; i < C_; i += blockDim.x) {
        float v = src[i] * r;
        g_x [(size_t)row * C_ + i] = v;
        g_x0[(size_t)row * C_ + i] = v;
    }
}

// ---------------- x = rl*x + xl*x0 (optional); xn = rmsnorm(x) ----------------
__global__ void mix_norm_kernel(const float* lr, const float* lx, int layer) {
    int row = blockIdx.x;
    float a = lr ? lr[layer] : 1.0f;
    float b = lx ? lx[layer] : 0.0f;
    float*       xr  = g_x  + (size_t)row * C_;
    const float* x0r = g_x0 + (size_t)row * C_;
    float s = 0.f;
    for (int i = threadIdx.x; i < C_; i += blockDim.x) {
        float v = a * xr[i] + b * x0r[i];
        xr[i] = v;
        s += v * v;
    }
    s = block_sum(s);
    float r = rsqrtf(s * (1.0f / C_) + EPS_);
    for (int i = threadIdx.x; i < C_; i += blockDim.x)
        g_xn[(size_t)row * C_ + i] = xr[i] * r;
}

// ---------------- tensor-core 3xTF32 GEMM ----------------
// C[M,N] = A[M,K] @ B[K,N] (+ D residual)
// mode 0: plain; mode 1: softcap; mode 2: relu^2
// Block 128x128, Ktile 32, 8 warps (2x4), warp tile 64x32, mma m16n8k8 tf32.
// Requires: M % 128 == 0, K % 32 == 0, N % 4 == 0, 16B-aligned rows.
__global__ __launch_bounds__(256, 1) void gemm_tc(
    const float* __restrict__ A, const float* __restrict__ Bm,
    float* __restrict__ C, const float* __restrict__ D,
    int M, int N, int K, int lda, int ldb, int ldc, int mode)
{
    __shared__ float As[128 * 36];   // [m][k], pitch 36 -> bank = (4g + t4) conflict-free
    __shared__ float Bs[32 * 136];   // [k][n], pitch 136 -> bank = (8t4 + g) conflict-free

    int tid = threadIdx.x;
    int wid = tid >> 5, lane = tid & 31;
    int g = lane >> 2, t4 = lane & 3;
    int warp_m = wid >> 2;           // 0..1
    int warp_n = wid & 3;            // 0..3
    int m0 = blockIdx.x * 128;
    int n0 = blockIdx.y * 128;

    float4 acc[4][4];
#pragma unroll
    for (int i = 0; i < 4; i++)
#pragma unroll
        for (int j = 0; j < 4; j++)
            acc[i][j] = make_float4(0.f, 0.f, 0.f, 0.f);

    for (int kt = 0; kt < K; kt += 32) {
        // ---- load A tile 128x32 (always in-bounds) ----
#pragma unroll
        for (int r = 0; r < 4; ++r) {
            int idx = tid + r * 256;          // 0..1023
            int m = idx >> 3, kq = idx & 7;
            float4 f = *reinterpret_cast<const float4*>(
                A + (size_t)(m0 + m) * lda + kt + kq * 4);
            *reinterpret_cast<float4*>(&As[m * 36 + kq * 4]) = f;
        }
        // ---- load B tile 32x128 (n guarded) ----
#pragma unroll
        for (int r = 0; r < 4; ++r) {
            int idx = tid + r * 256;
            int k = idx >> 5, nq = idx & 31;
            int n = n0 + nq * 4;
            float4 f = make_float4(0.f, 0.f, 0.f, 0.f);
            if (n < N)
                f = *reinterpret_cast<const float4*>(
                    Bm + (size_t)(kt + k) * ldb + n);
            *reinterpret_cast<float4*>(&Bs[k * 136 + nq * 4]) = f;
        }
        __syncthreads();

#pragma unroll
        for (int s = 0; s < 4; ++s) {
            uint32_t Ah[4][4], Al[4][4], Bh[4][2], Bl[4][2];
#pragma unroll
            for (int mi = 0; mi < 4; ++mi) {
                int r0 = warp_m * 64 + mi * 16 + g;
                float x0 = As[r0 * 36 + s * 8 + t4];
                float x1 = As[(r0 + 8) * 36 + s * 8 + t4];
                float x2 = As[r0 * 36 + s * 8 + t4 + 4];
                float x3 = As[(r0 + 8) * 36 + s * 8 + t4 + 4];
                split1(x0, Ah[mi][0], Al[mi][0]);
                split1(x1, Ah[mi][1], Al[mi][1]);
                split1(x2, Ah[mi][2], Al[mi][2]);
                split1(x3, Ah[mi][3], Al[mi][3]);
            }
#pragma unroll
            for (int ni = 0; ni < 4; ++ni) {
                int n = warp_n * 32 + ni * 8 + g;
                float y0 = Bs[(s * 8 + t4) * 136 + n];
                float y1 = Bs[(s * 8 + t4 + 4) * 136 + n];
                split1(y0, Bh[ni][0], Bl[ni][0]);
                split1(y1, Bh[ni][1], Bl[ni][1]);
            }
#pragma unroll
            for (int mi = 0; mi < 4; ++mi)
#pragma unroll
                for (int ni = 0; ni < 4; ++ni) {
                    mma8(acc[mi][ni], Ah[mi][0], Ah[mi][1], Ah[mi][2], Ah[mi][3],
                         Bh[ni][0], Bh[ni][1]);
                    mma8(acc[mi][ni], Ah[mi][0], Ah[mi][1], Ah[mi][2], Ah[mi][3],
                         Bl[ni][0], Bl[ni][1]);
                    mma8(acc[mi][ni], Al[mi][0], Al[mi][1], Al[mi][2], Al[mi][3],
                         Bh[ni][0], Bh[ni][1]);
                }
        }
        __syncthreads();
    }

    // ---- epilogue ----
#pragma unroll
    for (int mi = 0; mi < 4; ++mi) {
        int r0 = m0 + warp_m * 64 + mi * 16 + g;
#pragma unroll
        for (int ni = 0; ni < 4; ++ni) {
            int col = n0 + warp_n * 32 + ni * 8 + 2 * t4;
            if (col >= N) continue;
            float4 v = acc[mi][ni];
            if (D) {
                float2 d0 = *reinterpret_cast<const float2*>(D + (size_t)r0 * ldc + col);
                float2 d1 = *reinterpret_cast<const float2*>(D + (size_t)(r0 + 8) * ldc + col);
                v.x += d0.x; v.y += d0.y; v.z += d1.x; v.w += d1.y;
            }
            if (mode == 1) {
                v.x = 15.0f * tanhf(v.x * (1.f / 15.f));
                v.y = 15.0f * tanhf(v.y * (1.f / 15.f));
                v.z = 15.0f * tanhf(v.z * (1.f / 15.f));
                v.w = 15.0f * tanhf(v.w * (1.f / 15.f));
            } else if (mode == 2) {
                v.x = (v.x > 0.f) ? v.x * v.x : 0.f;
                v.y = (v.y > 0.f) ? v.y * v.y : 0.f;
                v.z = (v.z > 0.f) ? v.z * v.z : 0.f;
                v.w = (v.w > 0.f) ? v.w * v.w : 0.f;
            }
            *reinterpret_cast<float2*>(C + (size_t)r0 * ldc + col) = make_float2(v.x, v.y);
            *reinterpret_cast<float2*>(C + (size_t)(r0 + 8) * ldc + col) = make_float2(v.z, v.w);
        }
    }
}

// ---------------- per-token q/k/v build: gate, rope, per-head rmsnorm ------
__global__ void build_qkv_kernel(const int* __restrict__ idx,
                                 const float* __restrict__ cosp, const float* __restrict__ sinp,
                                 const float* __restrict__ vg, const float* __restrict__ vetab)
{
    int row = blockIdx.x;
    int h    = threadIdx.x >> 5;
    int lane = threadIdx.x & 31;
    const float* cosr = cosp + (size_t)row * (DR_ / 2);
    const float* sinr = sinp + (size_t)row * (DR_ / 2);

    float gv = g_xn[(size_t)row * C_ + lane] * vg[lane * H_ + h];
    gv = warp_sum(gv);
    float gate = 2.0f / (1.0f + __expf(-gv));

    int r16 = (lane < 16) ? lane : lane - 16;
    float c = cosr[r16], s = sinr[r16];

    float kn = g_kv[(size_t)row * KVW + h * 96 + lane];
    const float* dro = g_down + (size_t)row * DOWNW + 512;
    float kr = (lane < 16) ? (dro[lane] * c + dro[lane + 16] * s)
                           : (-dro[lane - 16] * s + dro[lane] * c);
    float ssk = warp_sum(kn * kn + kr * kr);
    float rk = rsqrtf(ssk * (1.0f / 64.0f) + EPS_);
    g_k[(size_t)row * C_ + h * 64 + lane]      = kn * rk;
    g_k[(size_t)row * C_ + h * 64 + lane + 32] = kr * rk;

    const float* qp = g_qpre + (size_t)row * C_ + h * 64;
    float qn = qp[lane];
    float qr = (lane < 16) ? (qp[32 + lane] * c + qp[48 + lane] * s)
                           : (-qp[16 + lane] * s + qp[32 + lane] * c);
    float ssq = warp_sum(qn * qn + qr * qr);
    float rq = rsqrtf(ssq * (1.0f / 64.0f) + EPS_);
    g_q[(size_t)row * C_ + h * 64 + lane]      = qn * rq;
    g_q[(size_t)row * C_ + h * 64 + lane + 32] = qr * rq;

    int tok = idx[row];
    const float* ver = vetab + (size_t)tok * C_ + h * 64;
    const float* kvv = g_kv + (size_t)row * KVW + h * 96 + 32;
    g_v[(size_t)row * C_ + h * 64 + lane]      = kvv[lane]      + gate * ver[lane];
    g_v[(size_t)row * C_ + h * 64 + lane + 32] = kvv[lane + 32] + gate * ver[lane + 32];
}

// ---------------- causal flash attention (fp32, online softmax) ------------
__global__ void attn_kernel()
{
    __shared__ float Qs[64][65];
    __shared__ float Ks[32][65];
    __shared__ float VsT[64][33];
    __shared__ float Ps[64][33];

    int q0 = blockIdx.x * 64;
    int h  = blockIdx.y;
    int b  = blockIdx.z;
    int tid = threadIdx.x;
    int tx = tid & 15, ty = tid >> 4;

    for (int i = tid; i < 64 * 64; i += 256) {
        int r = i >> 6, d = i & 63;
        Qs[r][d] = g_q[((size_t)(b * T_ + q0 + r) * H_ + h) * HD_ + d];
    }

    float m[4], l[4], acc[4][4];
#pragma unroll
    for (int i = 0; i < 4; i++) {
        m[i] = -1e30f; l[i] = 0.f;
#pragma unroll
        for (int j = 0; j < 4; j++) acc[i][j] = 0.f;
    }
    __syncthreads();

    for (int k0 = 0; k0 <= q0 + 32; k0 += 32) {
        for (int i = tid; i < 32 * 64; i += 256) {
            int r = i >> 6, d = i & 63;
            float v = g_k[((size_t)(b * T_ + k0 + r) * H_ + h) * HD_ + d];
            float w = g_v[((size_t)(b * T_ + k0 + r) * H_ + h) * HD_ + d];
            Ks[r][d]  = v;
            VsT[d][r] = w;
        }
        __syncthreads();

        float sv[4][2] = {};
#pragma unroll
        for (int d = 0; d < 64; d++) {
            float a0 = Qs[ty * 4 + 0][d], a1 = Qs[ty * 4 + 1][d];
            float a2 = Qs[ty * 4 + 2][d], a3 = Qs[ty * 4 + 3][d];
            float b0 = Ks[tx * 2 + 0][d], b1 = Ks[tx * 2 + 1][d];
            sv[0][0] += a0 * b0; sv[0][1] += a0 * b1;
            sv[1][0] += a1 * b0; sv[1][1] += a1 * b1;
            sv[2][0] += a2 * b0; sv[2][1] += a2 * b1;
            sv[3][0] += a3 * b0; sv[3][1] += a3 * b1;
        }

#pragma unroll
        for (int i = 0; i < 4; i++) {
            int qi = q0 + ty * 4 + i;
#pragma unroll
            for (int j = 0; j < 2; j++) {
                int ki = k0 + tx * 2 + j;
                sv[i][j] = (ki <= qi) ? sv[i][j] * 0.125f : -1e30f;
            }
            float rm = fmaxf(sv[i][0], sv[i][1]);
            rm = fmaxf(rm, __shfl_xor_sync(0xffffffffu, rm, 8, 16));
            rm = fmaxf(rm, __shfl_xor_sync(0xffffffffu, rm, 4, 16));
            rm = fmaxf(rm, __shfl_xor_sync(0xffffffffu, rm, 2, 16));
            rm = fmaxf(rm, __shfl_xor_sync(0xffffffffu, rm, 1, 16));
            float mn = fmaxf(m[i], rm);
            float corr = __expf(m[i] - mn);
            float p0 = __expf(sv[i][0] - mn);
            float p1 = __expf(sv[i][1] - mn);
            float rs = p0 + p1;
            rs += __shfl_xor_sync(0xffffffffu, rs, 8, 16);
            rs += __shfl_xor_sync(0xffffffffu, rs, 4, 16);
            rs += __shfl_xor_sync(0xffffffffu, rs, 2, 16);
            rs += __shfl_xor_sync(0xffffffffu, rs, 1, 16);
            l[i] = l[i] * corr + rs;
            m[i] = mn;
#pragma unroll
            for (int j = 0; j < 4; j++) acc[i][j] *= corr;
            Ps[ty * 4 + i][tx * 2 + 0] = p0;
            Ps[ty * 4 + i][tx * 2 + 1] = p1;
        }
        __syncwarp();

#pragma unroll
        for (int k = 0; k < 32; k++) {
            float a0 = Ps[ty * 4 + 0][k], a1 = Ps[ty * 4 + 1][k];
            float a2 = Ps[ty * 4 + 2][k], a3 = Ps[ty * 4 + 3][k];
            float b0 = VsT[tx * 4 + 0][k], b1 = VsT[tx * 4 + 1][k];
            float b2 = VsT[tx * 4 + 2][k], b3 = VsT[tx * 4 + 3][k];
            acc[0][0] += a0 * b0; acc[0][1] += a0 * b1; acc[0][2] += a0 * b2; acc[0][3] += a0 * b3;
            acc[1][0] += a1 * b0; acc[1][1] += a1 * b1; acc[1][2] += a1 * b2; acc[1][3] += a1 * b3;
            acc[2][0] += a2 * b0; acc[2][1] += a2 * b1; acc[2][2] += a2 * b2; acc[2][3] += a2 * b3;
            acc[3][0] += a3 * b0; acc[3][1] += a3 * b1; acc[3][2] += a3 * b2; acc[3][3] += a3 * b3;
        }
        __syncthreads();
    }

#pragma unroll
    for (int i = 0; i < 4; i++) {
        float inv = 1.0f / l[i];
        int r = q0 + ty * 4 + i;
#pragma unroll
        for (int j = 0; j < 4; j++)
            g_y[((size_t)(b * T_ + r) * H_ + h) * HD_ + tx * 4 + j] = acc[i][j] * inv;
    }
}

// ---------------- host orchestration ----------------
extern "C" void kernel_launch(void* const* d_in, const int* in_sizes, int n_in,
                              void* d_out, int out_size)
{
    (void)in_sizes; (void)n_in; (void)out_size;
    const int*   idx  = (const int*)  d_in[0];
    const float* cosp = (const float*)d_in[1];
    const float* sinp = (const float*)d_in[2];
    const float* wte  = (const float*)d_in[3];
    const float* vemb = (const float*)d_in[4];
    const float* wd   = (const float*)d_in[5];
    const float* wukv = (const float*)d_in[6];
    const float* wuq  = (const float*)d_in[7];
    const float* vg   = (const float*)d_in[8];
    const float* ap   = (const float*)d_in[9];
    const float* fc   = (const float*)d_in[10];
    const float* pj   = (const float*)d_in[11];
    const float* lr   = (const float*)d_in[12];
    const float* lx   = (const float*)d_in[13];
    const float* lmh  = (const float*)d_in[14];
    float* out = (float*)d_out;

    float *px, *pxn, *pdown, *pkv, *pqpre, *py, *ph;
    cudaGetSymbolAddress((void**)&px,    g_x);
    cudaGetSymbolAddress((void**)&pxn,   g_xn);
    cudaGetSymbolAddress((void**)&pdown, g_down);
    cudaGetSymbolAddress((void**)&pkv,   g_kv);
    cudaGetSymbolAddress((void**)&pqpre, g_qpre);
    cudaGetSymbolAddress((void**)&py,    g_y);
    cudaGetSymbolAddress((void**)&ph,    g_h);

    const int GM = NTOK / 128;   // 16 m-blocks

    embed_kernel<<<NTOK, 256>>>(idx, wte);

    for (int l = 0; l < L_; l++) {
        mix_norm_kernel<<<NTOK, 256>>>(lr, lx, l);

        // down = xn @ wd[l]  [2048,1024]@[1024,544]
        gemm_tc<<<dim3(GM, (DOWNW + 127) / 128), 256>>>(
            pxn, wd + (size_t)l * C_ * DOWNW, pdown, nullptr,
            NTOK, DOWNW, C_, C_, DOWNW, DOWNW, 0);

        // kv = down[:, :256] @ wukv[l]  [2048,256]@[256,1536]
        gemm_tc<<<dim3(GM, KVW / 128), 256>>>(
            pdown, wukv + (size_t)l * DC_ * KVW, pkv, nullptr,
            NTOK, KVW, DC_, DOWNW, KVW, KVW, 0);

        // qpre = down[:, 256:512] @ wuq[l]  [2048,256]@[256,1024]
        gemm_tc<<<dim3(GM, C_ / 128), 256>>>(
            pdown + DC_, wuq + (size_t)l * DC1_ * C_, pqpre, nullptr,
            NTOK, C_, DC1_, DOWNW, C_, C_, 0);

        build_qkv_kernel<<<NTOK, 512>>>(idx, cosp, sinp,
                                        vg + (size_t)l * 32 * H_,
                                        vemb + (size_t)l * V_ * C_);

        attn_kernel<<<dim3(T_ / 64, H_, B_), 256>>>();

        // x += y @ ap[l]
        gemm_tc<<<dim3(GM, C_ / 128), 256>>>(
            py, ap + (size_t)l * C_ * C_, px, px,
            NTOK, C_, C_, C_, C_, C_, 0);

        mix_norm_kernel<<<NTOK, 256>>>(nullptr, nullptr, 0);

        // h = relu(xn @ fc[l])^2  [2048,1024]@[1024,4096], fused relu^2
        gemm_tc<<<dim3(GM, 4 * C_ / 128), 256>>>(
            pxn, fc + (size_t)l * C_ * 4 * C_, ph, nullptr,
            NTOK, 4 * C_, C_, C_, 4 * C_, 4 * C_, 2);

        // x += h @ pj[l]  [2048,4096]@[4096,1024]
        gemm_tc<<<dim3(GM, C_ / 128), 256>>>(
            ph, pj + (size_t)l * 4 * C_ * C_, px, px,
            NTOK, C_, 4 * C_, 4 * C_, C_, C_, 0);
    }

    mix_norm_kernel<<<NTOK, 256>>>(nullptr, nullptr, 0);
    // out = softcap(xn @ lm_head)  [2048,1024]@[1024,32000]
    gemm_tc<<<dim3(GM, V_ / 128), 256>>>(
        pxn, lmh, out, nullptr,
        NTOK, V_, C_, C_, V_, V_, 1);
}

// round 4
// speedup vs baseline: 3.5227x; 1.6250x over previous
#include <cuda_runtime.h>
#include <cuda_fp16.h>
#include <math.h>
#include <stdint.h>

// ---------------- problem constants ----------------
#define B_    2
#define T_    1024
#define C_    1024
#define H_    16
#define HD_   64
#define DC_   256
#define DC1_  256
#define DR_   32
#define DN_   32
#define V_    32000
#define L_    4
#define NTOK  (B_*T_)             // 2048
#define DOWNW (DC_+DC1_+DR_)      // 544
#define KVW   (H_*(DN_+HD_))      // 1536
#define EPS_  1.1920929e-07f

// ---------------- scratch ----------------
__device__ float g_x   [NTOK*C_];
__device__ float g_x0  [NTOK*C_];
__device__ float g_xn  [NTOK*C_];
__device__ float g_down[NTOK*DOWNW];
__device__ float g_kv  [NTOK*KVW];
__device__ float g_qpre[NTOK*C_];
__device__ float g_q   [NTOK*C_];
__device__ float g_k   [NTOK*C_];
__device__ float g_v   [NTOK*C_];
__device__ float g_y   [NTOK*C_];
__device__ float g_h   [NTOK*4*C_];

// ---------------- helpers ----------------
__device__ __forceinline__ uint32_t smem_u32(const void* p) {
    uint32_t a;
    asm("{ .reg .u64 t; cvta.to.shared.u64 t, %1; cvt.u32.u64 %0, t; }" : "=r"(a) : "l"(p));
    return a;
}
__device__ __forceinline__ float warp_sum(float v) {
    v += __shfl_xor_sync(0xffffffffu, v, 16);
    v += __shfl_xor_sync(0xffffffffu, v, 8);
    v += __shfl_xor_sync(0xffffffffu, v, 4);
    v += __shfl_xor_sync(0xffffffffu, v, 2);
    v += __shfl_xor_sync(0xffffffffu, v, 1);
    return v;
}
__device__ __forceinline__ float block_sum(float v) {
    __shared__ float sh[32];
    int lane = threadIdx.x & 31, wid = threadIdx.x >> 5;
    v = warp_sum(v);
    if (lane == 0) sh[wid] = v;
    __syncthreads();
    int nw = blockDim.x >> 5;
    if (wid == 0) {
        float t = (lane < nw) ? sh[lane] : 0.f;
        t = warp_sum(t);
        if (lane == 0) sh[0] = t;
    }
    __syncthreads();
    return sh[0];
}

// ---------------- mma / ldmatrix wrappers ----------------
__device__ __forceinline__ void ldsm_x4(uint32_t* r, uint32_t addr) {
    asm volatile("ldmatrix.sync.aligned.m8n8.x4.shared.b16 {%0,%1,%2,%3}, [%4];"
                 : "=r"(r[0]), "=r"(r[1]), "=r"(r[2]), "=r"(r[3]) : "r"(addr));
}
__device__ __forceinline__ void ldsm_x2t(uint32_t* r, uint32_t addr) {
    asm volatile("ldmatrix.sync.aligned.m8n8.x2.trans.shared.b16 {%0,%1}, [%2];"
                 : "=r"(r[0]), "=r"(r[1]) : "r"(addr));
}
__device__ __forceinline__ void mma16816(float4& d, const uint32_t* a, const uint32_t* b) {
    asm volatile(
        "mma.sync.aligned.m16n8k16.row.col.f32.f16.f16.f32 "
        "{%0,%1,%2,%3},{%4,%5,%6,%7},{%8,%9},{%0,%1,%2,%3};"
        : "+f"(d.x), "+f"(d.y), "+f"(d.z), "+f"(d.w)
        : "r"(a[0]), "r"(a[1]), "r"(a[2]), "r"(a[3]), "r"(b[0]), "r"(b[1]));
}

// split fp32 -> (hi, lo) fp16 pair
__device__ __forceinline__ void splith(float x, uint16_t& hi, uint16_t& lo) {
    __half h = __float2half_rn(x);
    float r = x - __half2float(h);
    __half l = __float2half_rn(r);
    hi = __half_as_ushort(h);
    lo = __half_as_ushort(l);
}

// ---------------- embedding + rmsnorm ----------------
__global__ void embed_kernel(const int* __restrict__ idx, const float* __restrict__ wte) {
    int row = blockIdx.x;
    int tok = idx[row];
    const float* src = wte + (size_t)tok * C_;
    float s = 0.f;
    for (int i = threadIdx.x; i < C_; i += blockDim.x) { float v = src[i]; s += v * v; }
    s = block_sum(s);
    float r = rsqrtf(s * (1.0f / C_) + EPS_);
    for (int i = threadIdx.x; i < C_; i += blockDim.x) {
        float v = src[i] * r;
        g_x [(size_t)row * C_ + i] = v;
        g_x0[(size_t)row * C_ + i] = v;
    }
}

__global__ void mix_norm_kernel(const float* lr, const float* lx, int layer) {
    int row = blockIdx.x;
    float a = lr ? lr[layer] : 1.0f;
    float b = lx ? lx[layer] : 0.0f;
    float*       xr  = g_x  + (size_t)row * C_;
    const float* x0r = g_x0 + (size_t)row * C_;
    float s = 0.f;
    for (int i = threadIdx.x; i < C_; i += blockDim.x) {
        float v = a * xr[i] + b * x0r[i];
        xr[i] = v;
        s += v * v;
    }
    s = block_sum(s);
    float r = rsqrtf(s * (1.0f / C_) + EPS_);
    for (int i = threadIdx.x; i < C_; i += blockDim.x)
        g_xn[(size_t)row * C_ + i] = xr[i] * r;
}

// ---------------- 3xFP16 tensor-core GEMM ----------------
// C[M,N] = A[M,K] @ B[K,N] (+D). mode 0 plain, 1 softcap, 2 relu^2.
// CTA 128x128, Ktile 64, 8 warps (2x4), warp tile 64x32.
// SMEM per stage: Ahi/Alo planes [128m][64k] half (SW128 swizzle, 128B rows),
//                 Bhi/Blo planes [64k][128n] half (chunk^k swizzle, 256B rows).
#define KT_    64
#define APL_   16384
#define BPL_   16384
#define STG_   (2*APL_ + 2*BPL_)     // 64KB per stage

__global__ __launch_bounds__(256, 1) void gemm_h3(
    const float* __restrict__ A, const float* __restrict__ Bm,
    float* __restrict__ C, const float* __restrict__ D,
    int M, int N, int K, int lda, int ldb, int ldc, int mode)
{
    extern __shared__ __align__(1024) char sm[];
    int tid = threadIdx.x;
    int wid = tid >> 5, lane = tid & 31;
    int warp_m = wid >> 2, warp_n = wid & 3;
    int m0 = blockIdx.x * 128, n0 = blockIdx.y * 128;
    uint32_t smb = smem_u32(sm);

    // accumulators
    float4 acc[4][4];
#pragma unroll
    for (int i = 0; i < 4; i++)
#pragma unroll
        for (int j = 0; j < 4; j++) acc[i][j] = make_float4(0.f, 0.f, 0.f, 0.f);

    // producer index precompute (8 float4 each for A and B per thread)
    int a_row[8], a_kq[8], b_k[8], b_nq[8];
#pragma unroll
    for (int r = 0; r < 8; r++) {
        int f = tid + r * 256;
        a_row[r] = f >> 4;  a_kq[r] = f & 15;
        b_k[r]   = f >> 5;  b_nq[r] = f & 31;
    }

    // fragment address precompute
    int arow = warp_m * 64 + (lane & 15);     // + mi*16
    int akof = (lane & 16);                   // byte offset 0/16
    int bkrl = (lane & 15);                   // + ks*16
    int bnof = warp_n * 64;                   // + ni*16 bytes

    float4 ar[8], br[8];
    int nk = K / KT_;

    // ---- prologue: load + split ktile 0 ----
    {
        const float* Ab = A + (size_t)m0 * lda;
        const float* Bb = Bm + n0;
#pragma unroll
        for (int r = 0; r < 8; r++)
            ar[r] = *reinterpret_cast<const float4*>(Ab + (size_t)a_row[r] * lda + a_kq[r] * 4);
#pragma unroll
        for (int r = 0; r < 8; r++) {
            int n = b_nq[r] * 4;
            br[r] = (n0 + n < N)
                ? *reinterpret_cast<const float4*>(Bb + (size_t)b_k[r] * ldb + n)
                : make_float4(0.f, 0.f, 0.f, 0.f);
        }
        char* Ah = sm;              char* Al = sm + APL_;
        char* Bh = sm + 2 * APL_;   char* Bl = sm + 2 * APL_ + BPL_;
#pragma unroll
        for (int r = 0; r < 8; r++) {
            uint16_t h0,l0,h1,l1,h2,l2,h3,l3;
            splith(ar[r].x,h0,l0); splith(ar[r].y,h1,l1);
            splith(ar[r].z,h2,l2); splith(ar[r].w,h3,l3);
            uint32_t off = a_row[r] * 128 + a_kq[r] * 8;
            off ^= (off >> 3) & 0x70;
            *reinterpret_cast<uint2*>(Ah + off) =
                make_uint2((uint32_t)h0 | ((uint32_t)h1 << 16), (uint32_t)h2 | ((uint32_t)h3 << 16));
            *reinterpret_cast<uint2*>(Al + off) =
                make_uint2((uint32_t)l0 | ((uint32_t)l1 << 16), (uint32_t)l2 | ((uint32_t)l3 << 16));
        }
#pragma unroll
        for (int r = 0; r < 8; r++) {
            uint16_t h0,l0,h1,l1,h2,l2,h3,l3;
            splith(br[r].x,h0,l0); splith(br[r].y,h1,l1);
            splith(br[r].z,h2,l2); splith(br[r].w,h3,l3);
            uint32_t off = (b_k[r] * 256 + b_nq[r] * 8) ^ ((uint32_t)(b_k[r] & 7) << 4);
            *reinterpret_cast<uint2*>(Bh + off) =
                make_uint2((uint32_t)h0 | ((uint32_t)h1 << 16), (uint32_t)h2 | ((uint32_t)h3 << 16));
            *reinterpret_cast<uint2*>(Bl + off) =
                make_uint2((uint32_t)l0 | ((uint32_t)l1 << 16), (uint32_t)l2 | ((uint32_t)l3 << 16));
        }
    }
    __syncthreads();

    for (int kt = 0; kt < nk; kt++) {
        int p = kt & 1;
        // ---- prefetch next ktile into registers ----
        if (kt + 1 < nk) {
            const float* Ab = A + (size_t)m0 * lda + (kt + 1) * KT_;
            const float* Bb = Bm + (size_t)((kt + 1) * KT_) * ldb + n0;
#pragma unroll
            for (int r = 0; r < 8; r++)
                ar[r] = *reinterpret_cast<const float4*>(Ab + (size_t)a_row[r] * lda + a_kq[r] * 4);
#pragma unroll
            for (int r = 0; r < 8; r++) {
                int n = b_nq[r] * 4;
                br[r] = (n0 + n < N)
                    ? *reinterpret_cast<const float4*>(Bb + (size_t)b_k[r] * ldb + n)
                    : make_float4(0.f, 0.f, 0.f, 0.f);
            }
        }

        // ---- mma over stage p ----
        uint32_t sAh = smb + p * STG_;
        uint32_t sAl = sAh + APL_;
        uint32_t sBh = sAh + 2 * APL_;
        uint32_t sBl = sBh + BPL_;
#pragma unroll
        for (int ks = 0; ks < 4; ks++) {
            uint32_t ahi[4][4], alo[4][4], bhi[4][2], blo[4][2];
#pragma unroll
            for (int mi = 0; mi < 4; mi++) {
                uint32_t off = (uint32_t)((arow + mi * 16) * 128 + ks * 32 + akof);
                off ^= (off >> 3) & 0x70;
                ldsm_x4(ahi[mi], sAh + off);
                ldsm_x4(alo[mi], sAl + off);
            }
#pragma unroll
            for (int ni = 0; ni < 4; ni++) {
                int krow = ks * 16 + bkrl;
                uint32_t off = (uint32_t)(krow * 256 + bnof + ni * 16) ^ ((uint32_t)(krow & 7) << 4);
                ldsm_x2t(bhi[ni], sBh + off);
                ldsm_x2t(blo[ni], sBl + off);
            }
#pragma unroll
            for (int mi = 0; mi < 4; mi++)
#pragma unroll
                for (int ni = 0; ni < 4; ni++) {
                    mma16816(acc[mi][ni], ahi[mi], bhi[ni]);
                    mma16816(acc[mi][ni], ahi[mi], blo[ni]);
                    mma16816(acc[mi][ni], alo[mi], bhi[ni]);
                }
        }

        // ---- split + store next stage ----
        if (kt + 1 < nk) {
            int q = p ^ 1;
            char* Ah = sm + q * STG_;          char* Al = Ah + APL_;
            char* Bh = Ah + 2 * APL_;          char* Bl = Ah + 2 * APL_ + BPL_;
#pragma unroll
            for (int r = 0; r < 8; r++) {
                uint16_t h0,l0,h1,l1,h2,l2,h3,l3;
                splith(ar[r].x,h0,l0); splith(ar[r].y,h1,l1);
                splith(ar[r].z,h2,l2); splith(ar[r].w,h3,l3);
                uint32_t off = a_row[r] * 128 + a_kq[r] * 8;
                off ^= (off >> 3) & 0x70;
                *reinterpret_cast<uint2*>(Ah + off) =
                    make_uint2((uint32_t)h0 | ((uint32_t)h1 << 16), (uint32_t)h2 | ((uint32_t)h3 << 16));
                *reinterpret_cast<uint2*>(Al + off) =
                    make_uint2((uint32_t)l0 | ((uint32_t)l1 << 16), (uint32_t)l2 | ((uint32_t)l3 << 16));
            }
#pragma unroll
            for (int r = 0; r < 8; r++) {
                uint16_t h0,l0,h1,l1,h2,l2,h3,l3;
                splith(br[r].x,h0,l0); splith(br[r].y,h1,l1);
                splith(br[r].z,h2,l2); splith(br[r].w,h3,l3);
                uint32_t off = (b_k[r] * 256 + b_nq[r] * 8) ^ ((uint32_t)(b_k[r] & 7) << 4);
                *reinterpret_cast<uint2*>(Bh + off) =
                    make_uint2((uint32_t)h0 | ((uint32_t)h1 << 16), (uint32_t)h2 | ((uint32_t)h3 << 16));
                *reinterpret_cast<uint2*>(Bl + off) =
                    make_uint2((uint32_t)l0 | ((uint32_t)l1 << 16), (uint32_t)l2 | ((uint32_t)l3 << 16));
            }
        }
        __syncthreads();
    }

    // ---- epilogue ----
    int g = lane >> 2, t4 = lane & 3;
#pragma unroll
    for (int mi = 0; mi < 4; mi++) {
        int r0 = m0 + warp_m * 64 + mi * 16 + g;
#pragma unroll
        for (int ni = 0; ni < 4; ni++) {
            int col = n0 + warp_n * 32 + ni * 8 + 2 * t4;
            if (col >= N) continue;
            float4 v = acc[mi][ni];
            if (D) {
                float2 d0 = *reinterpret_cast<const float2*>(D + (size_t)r0 * ldc + col);
                float2 d1 = *reinterpret_cast<const float2*>(D + (size_t)(r0 + 8) * ldc + col);
                v.x += d0.x; v.y += d0.y; v.z += d1.x; v.w += d1.y;
            }
            if (mode == 1) {
                v.x = 15.0f * tanhf(v.x * (1.f / 15.f));
                v.y = 15.0f * tanhf(v.y * (1.f / 15.f));
                v.z = 15.0f * tanhf(v.z * (1.f / 15.f));
                v.w = 15.0f * tanhf(v.w * (1.f / 15.f));
            } else if (mode == 2) {
                v.x = (v.x > 0.f) ? v.x * v.x : 0.f;
                v.y = (v.y > 0.f) ? v.y * v.y : 0.f;
                v.z = (v.z > 0.f) ? v.z * v.z : 0.f;
                v.w = (v.w > 0.f) ? v.w * v.w : 0.f;
            }
            *reinterpret_cast<float2*>(C + (size_t)r0 * ldc + col) = make_float2(v.x, v.y);
            *reinterpret_cast<float2*>(C + (size_t)(r0 + 8) * ldc + col) = make_float2(v.z, v.w);
        }
    }
}

// ---------------- per-token q/k/v build ----------------
__global__ void build_qkv_kernel(const int* __restrict__ idx,
                                 const float* __restrict__ cosp, const float* __restrict__ sinp,
                                 const float* __restrict__ vg, const float* __restrict__ vetab)
{
    int row = blockIdx.x;
    int h    = threadIdx.x >> 5;
    int lane = threadIdx.x & 31;
    const float* cosr = cosp + (size_t)row * (DR_ / 2);
    const float* sinr = sinp + (size_t)row * (DR_ / 2);

    float gv = g_xn[(size_t)row * C_ + lane] * vg[lane * H_ + h];
    gv = warp_sum(gv);
    float gate = 2.0f / (1.0f + __expf(-gv));

    int r16 = (lane < 16) ? lane : lane - 16;
    float c = cosr[r16], s = sinr[r16];

    float kn = g_kv[(size_t)row * KVW + h * 96 + lane];
    const float* dro = g_down + (size_t)row * DOWNW + 512;
    float kr = (lane < 16) ? (dro[lane] * c + dro[lane + 16] * s)
                           : (-dro[lane - 16] * s + dro[lane] * c);
    float ssk = warp_sum(kn * kn + kr * kr);
    float rk = rsqrtf(ssk * (1.0f / 64.0f) + EPS_);
    g_k[(size_t)row * C_ + h * 64 + lane]      = kn * rk;
    g_k[(size_t)row * C_ + h * 64 + lane + 32] = kr * rk;

    const float* qp = g_qpre + (size_t)row * C_ + h * 64;
    float qn = qp[lane];
    float qr = (lane < 16) ? (qp[32 + lane] * c + qp[48 + lane] * s)
                           : (-qp[16 + lane] * s + qp[32 + lane] * c);
    float ssq = warp_sum(qn * qn + qr * qr);
    float rq = rsqrtf(ssq * (1.0f / 64.0f) + EPS_);
    g_q[(size_t)row * C_ + h * 64 + lane]      = qn * rq;
    g_q[(size_t)row * C_ + h * 64 + lane + 32] = qr * rq;

    int tok = idx[row];
    const float* ver = vetab + (size_t)tok * C_ + h * 64;
    const float* kvv = g_kv + (size_t)row * KVW + h * 96 + 32;
    g_v[(size_t)row * C_ + h * 64 + lane]      = kvv[lane]      + gate * ver[lane];
    g_v[(size_t)row * C_ + h * 64 + lane + 32] = kvv[lane + 32] + gate * ver[lane + 32];
}

// ---------------- causal flash attention ----------------
__global__ void attn_kernel()
{
    __shared__ float Qs[64][65];
    __shared__ float Ks[32][65];
    __shared__ float VsT[64][33];
    __shared__ float Ps[64][33];

    int q0 = blockIdx.x * 64;
    int h  = blockIdx.y;
    int b  = blockIdx.z;
    int tid = threadIdx.x;
    int tx = tid & 15, ty = tid >> 4;

    for (int i = tid; i < 64 * 64; i += 256) {
        int r = i >> 6, d = i & 63;
        Qs[r][d] = g_q[((size_t)(b * T_ + q0 + r) * H_ + h) * HD_ + d];
    }

    float m[4], l[4], acc[4][4];
#pragma unroll
    for (int i = 0; i < 4; i++) {
        m[i] = -1e30f; l[i] = 0.f;
#pragma unroll
        for (int j = 0; j < 4; j++) acc[i][j] = 0.f;
    }
    __syncthreads();

    for (int k0 = 0; k0 <= q0 + 32; k0 += 32) {
        for (int i = tid; i < 32 * 64; i += 256) {
            int r = i >> 6, d = i & 63;
            float v = g_k[((size_t)(b * T_ + k0 + r) * H_ + h) * HD_ + d];
            float w = g_v[((size_t)(b * T_ + k0 + r) * H_ + h) * HD_ + d];
            Ks[r][d]  = v;
            VsT[d][r] = w;
        }
        __syncthreads();

        float sv[4][2] = {};
#pragma unroll
        for (int d = 0; d < 64; d++) {
            float a0 = Qs[ty * 4 + 0][d], a1 = Qs[ty * 4 + 1][d];
            float a2 = Qs[ty * 4 + 2][d], a3 = Qs[ty * 4 + 3][d];
            float b0 = Ks[tx * 2 + 0][d], b1 = Ks[tx * 2 + 1][d];
            sv[0][0] += a0 * b0; sv[0][1] += a0 * b1;
            sv[1][0] += a1 * b0; sv[1][1] += a1 * b1;
            sv[2][0] += a2 * b0; sv[2][1] += a2 * b1;
            sv[3][0] += a3 * b0; sv[3][1] += a3 * b1;
        }

#pragma unroll
        for (int i = 0; i < 4; i++) {
            int qi = q0 + ty * 4 + i;
#pragma unroll
            for (int j = 0; j < 2; j++) {
                int ki = k0 + tx * 2 + j;
                sv[i][j] = (ki <= qi) ? sv[i][j] * 0.125f : -1e30f;
            }
            float rm = fmaxf(sv[i][0], sv[i][1]);
            rm = fmaxf(rm, __shfl_xor_sync(0xffffffffu, rm, 8, 16));
            rm = fmaxf(rm, __shfl_xor_sync(0xffffffffu, rm, 4, 16));
            rm = fmaxf(rm, __shfl_xor_sync(0xffffffffu, rm, 2, 16));
            rm = fmaxf(rm, __shfl_xor_sync(0xffffffffu, rm, 1, 16));
            float mn = fmaxf(m[i], rm);
            float corr = __expf(m[i] - mn);
            float p0 = __expf(sv[i][0] - mn);
            float p1 = __expf(sv[i][1] - mn);
            float rs = p0 + p1;
            rs += __shfl_xor_sync(0xffffffffu, rs, 8, 16);
            rs += __shfl_xor_sync(0xffffffffu, rs, 4, 16);
            rs += __shfl_xor_sync(0xffffffffu, rs, 2, 16);
            rs += __shfl_xor_sync(0xffffffffu, rs, 1, 16);
            l[i] = l[i] * corr + rs;
            m[i] = mn;
#pragma unroll
            for (int j = 0; j < 4; j++) acc[i][j] *= corr;
            Ps[ty * 4 + i][tx * 2 + 0] = p0;
            Ps[ty * 4 + i][tx * 2 + 1] = p1;
        }
        __syncwarp();

#pragma unroll
        for (int k = 0; k < 32; k++) {
            float a0 = Ps[ty * 4 + 0][k], a1 = Ps[ty * 4 + 1][k];
            float a2 = Ps[ty * 4 + 2][k], a3 = Ps[ty * 4 + 3][k];
            float b0 = VsT[tx * 4 + 0][k], b1 = VsT[tx * 4 + 1][k];
            float b2 = VsT[tx * 4 + 2][k], b3 = VsT[tx * 4 + 3][k];
            acc[0][0] += a0 * b0; acc[0][1] += a0 * b1; acc[0][2] += a0 * b2; acc[0][3] += a0 * b3;
            acc[1][0] += a1 * b0; acc[1][1] += a1 * b1; acc[1][2] += a1 * b2; acc[1][3] += a1 * b3;
            acc[2][0] += a2 * b0; acc[2][1] += a2 * b1; acc[2][2] += a2 * b2; acc[2][3] += a2 * b3;
            acc[3][0] += a3 * b0; acc[3][1] += a3 * b1; acc[3][2] += a3 * b2; acc[3][3] += a3 * b3;
        }
        __syncthreads();
    }

#pragma unroll
    for (int i = 0; i < 4; i++) {
        float inv = 1.0f / l[i];
        int r = q0 + ty * 4 + i;
#pragma unroll
        for (int j = 0; j < 4; j++)
            g_y[((size_t)(b * T_ + r) * H_ + h) * HD_ + tx * 4 + j] = acc[i][j] * inv;
    }
}

// ---------------- host orchestration ----------------
extern "C" void kernel_launch(void* const* d_in, const int* in_sizes, int n_in,
                              void* d_out, int out_size)
{
    (void)in_sizes; (void)n_in; (void)out_size;
    const int*   idx  = (const int*)  d_in[0];
    const float* cosp = (const float*)d_in[1];
    const float* sinp = (const float*)d_in[2];
    const float* wte  = (const float*)d_in[3];
    const float* vemb = (const float*)d_in[4];
    const float* wd   = (const float*)d_in[5];
    const float* wukv = (const float*)d_in[6];
    const float* wuq  = (const float*)d_in[7];
    const float* vg   = (const float*)d_in[8];
    const float* ap   = (const float*)d_in[9];
    const float* fc   = (const float*)d_in[10];
    const float* pj   = (const float*)d_in[11];
    const float* lr   = (const float*)d_in[12];
    const float* lx   = (const float*)d_in[13];
    const float* lmh  = (const float*)d_in[14];
    float* out = (float*)d_out;

    float *px, *pxn, *pdown, *pkv, *pqpre, *py, *ph;
    cudaGetSymbolAddress((void**)&px,    g_x);
    cudaGetSymbolAddress((void**)&pxn,   g_xn);
    cudaGetSymbolAddress((void**)&pdown, g_down);
    cudaGetSymbolAddress((void**)&pkv,   g_kv);
    cudaGetSymbolAddress((void**)&pqpre, g_qpre);
    cudaGetSymbolAddress((void**)&py,    g_y);
    cudaGetSymbolAddress((void**)&ph,    g_h);

    const int SMEMSZ = 2 * STG_;   // 128 KB
    static int attr_set = 0;
    cudaFuncSetAttribute(gemm_h3, cudaFuncAttributeMaxDynamicSharedMemorySize, SMEMSZ);
    (void)attr_set;

    const int GM = NTOK / 128;     // 16 m-blocks

    embed_kernel<<<NTOK, 256>>>(idx, wte);

    for (int l = 0; l < L_; l++) {
        mix_norm_kernel<<<NTOK, 256>>>(lr, lx, l);

        // down = xn @ wd[l]  [2048,1024]@[1024,544]
        gemm_h3<<<dim3(GM, (DOWNW + 127) / 128), 256, SMEMSZ>>>(
            pxn, wd + (size_t)l * C_ * DOWNW, pdown, nullptr,
            NTOK, DOWNW, C_, C_, DOWNW, DOWNW, 0);

        // kv = down[:, :256] @ wukv[l]  [2048,256]@[256,1536]
        gemm_h3<<<dim3(GM, KVW / 128), 256, SMEMSZ>>>(
            pdown, wukv + (size_t)l * DC_ * KVW, pkv, nullptr,
            NTOK, KVW, DC_, DOWNW, KVW, KVW, 0);

        // qpre = down[:, 256:512] @ wuq[l]  [2048,256]@[256,1024]
        gemm_h3<<<dim3(GM, C_ / 128), 256, SMEMSZ>>>(
            pdown + DC_, wuq + (size_t)l * DC1_ * C_, pqpre, nullptr,
            NTOK, C_, DC1_, DOWNW, C_, C_, 0);

        build_qkv_kernel<<<NTOK, 512>>>(idx, cosp, sinp,
                                        vg + (size_t)l * 32 * H_,
                                        vemb + (size_t)l * V_ * C_);

        attn_kernel<<<dim3(T_ / 64, H_, B_), 256>>>();

        // x += y @ ap[l]
        gemm_h3<<<dim3(GM, C_ / 128), 256, SMEMSZ>>>(
            py, ap + (size_t)l * C_ * C_, px, px,
            NTOK, C_, C_, C_, C_, C_, 0);

        mix_norm_kernel<<<NTOK, 256>>>(nullptr, nullptr, 0);

        // h = relu(xn @ fc[l])^2
        gemm_h3<<<dim3(GM, 4 * C_ / 128), 256, SMEMSZ>>>(
            pxn, fc + (size_t)l * C_ * 4 * C_, ph, nullptr,
            NTOK, 4 * C_, C_, C_, 4 * C_, 4 * C_, 2);

        // x += h @ pj[l]
        gemm_h3<<<dim3(GM, C_ / 128), 256, SMEMSZ>>>(
            ph, pj + (size_t)l * 4 * C_ * C_, px, px,
            NTOK, C_, 4 * C_, 4 * C_, C_, C_, 0);
    }

    mix_norm_kernel<<<NTOK, 256>>>(nullptr, nullptr, 0);
    // out = softcap(xn @ lm_head)
    gemm_h3<<<dim3(GM, V_ / 128), 256, SMEMSZ>>>(
        pxn, lmh, out, nullptr,
        NTOK, V_, C_, C_, V_, V_, 1);
}